// round 7
// baseline (speedup 1.0000x reference)
#include <cuda_runtime.h>
#include <cuda_fp16.h>
#include <cuda_bf16.h>

#define N_NODES 100000
#define N_EDGES 1600000
#define NH      4
#define HD      128
#define NEG_SLOPE 0.2f
#define CHUNK   256
#define NCHUNK  ((N_NODES + CHUNK - 1) / CHUNK)   // 391

// ---------------- scratch (device globals: allocation-free) ----------------
__device__ __half g_fth[N_NODES * HD];  // projected features fp16 [N,128]
__device__ float  g_el [N_NODES * NH];  // left logits
__device__ float  g_er [N_NODES * NH];  // right logits
__device__ int    g_deg[N_NODES];
__device__ int    g_off[N_NODES];
__device__ int    g_cur[N_NODES];
__device__ int    g_csr_src[N_EDGES];
__device__ int    g_part[NCHUNK];

__device__ __forceinline__ float lrelu(float x) {
    return x > 0.f ? x : NEG_SLOPE * x;
}
__device__ __forceinline__ unsigned f2tf32(float f) {
    unsigned u;
    asm("cvt.rna.tf32.f32 %0, %1;" : "=r"(u) : "f"(f));
    return u;
}

// ---------------- tf32 tensor-core GEMM + fused el/er epilogue -------------
#define SMS 132
#define GEMM_SMEM (2 * 128 * SMS * 4)

__global__ __launch_bounds__(256, 1)
void gemm_kernel(const float* __restrict__ feat, const float* __restrict__ W,
                 const float* __restrict__ attn_l, const float* __restrict__ attn_r) {
    extern __shared__ unsigned su[];
    unsigned* sF = su;
    unsigned* sW = su + 128 * SMS;

    const int tid  = threadIdx.x;
    const int row0 = blockIdx.x * 128;

    for (int i = tid; i < 4096; i += 256) {
        float4 w = reinterpret_cast<const float4*>(W)[i];
        int base = i * 4;
        int n = base >> 7, k = base & 127;
        unsigned* d = &sW[n * SMS + k];
        d[0] = f2tf32(w.x); d[1] = f2tf32(w.y); d[2] = f2tf32(w.z); d[3] = f2tf32(w.w);
    }
    for (int i = tid; i < 4096; i += 256) {
        int base = i * 4;
        int r = base >> 7, k = base & 127;
        int gr = row0 + r;
        float4 f = (gr < N_NODES)
                 ? reinterpret_cast<const float4*>(feat)[gr * 32 + (k >> 2)]
                 : make_float4(0.f, 0.f, 0.f, 0.f);
        unsigned* d = &sF[r * SMS + k];
        d[0] = f2tf32(f.x); d[1] = f2tf32(f.y); d[2] = f2tf32(f.z); d[3] = f2tf32(f.w);
    }
    __syncthreads();

    const int warp = tid >> 5, lane = tid & 31;
    const int g = lane >> 2, t = lane & 3;
    const int mrow = warp * 16;

    float c[16][4];
#pragma unroll
    for (int nb = 0; nb < 16; nb++)
#pragma unroll
        for (int j = 0; j < 4; j++) c[nb][j] = 0.f;

#pragma unroll
    for (int ks = 0; ks < 16; ks++) {
        const int ko = ks * 8;
        unsigned a0 = sF[(mrow + g)     * SMS + ko + t];
        unsigned a1 = sF[(mrow + g + 8) * SMS + ko + t];
        unsigned a2 = sF[(mrow + g)     * SMS + ko + t + 4];
        unsigned a3 = sF[(mrow + g + 8) * SMS + ko + t + 4];
#pragma unroll
        for (int nb = 0; nb < 16; nb++) {
            unsigned b0 = sW[(nb * 8 + g) * SMS + ko + t];
            unsigned b1 = sW[(nb * 8 + g) * SMS + ko + t + 4];
            asm volatile(
                "mma.sync.aligned.m16n8k8.row.col.f32.tf32.tf32.f32 "
                "{%0,%1,%2,%3}, {%4,%5,%6,%7}, {%8,%9}, {%0,%1,%2,%3};"
                : "+f"(c[nb][0]), "+f"(c[nb][1]), "+f"(c[nb][2]), "+f"(c[nb][3])
                : "r"(a0), "r"(a1), "r"(a2), "r"(a3), "r"(b0), "r"(b1));
        }
    }

    const int r_lo = row0 + mrow + g;
    const int r_hi = r_lo + 8;

#pragma unroll
    for (int nb = 0; nb < 16; nb++) {
        int cc = nb * 8 + 2 * t;
        if (r_lo < N_NODES)
            *reinterpret_cast<__half2*>(&g_fth[r_lo * HD + cc]) =
                __floats2half2_rn(c[nb][0], c[nb][1]);
        if (r_hi < N_NODES)
            *reinterpret_cast<__half2*>(&g_fth[r_hi * HD + cc]) =
                __floats2half2_rn(c[nb][2], c[nb][3]);
    }

#pragma unroll
    for (int h = 0; h < 4; h++) {
        float pll = 0.f, plh = 0.f, prl = 0.f, prh = 0.f;
#pragma unroll
        for (int q = 0; q < 4; q++) {
            int nb = h * 4 + q;
            int cc = nb * 8 + 2 * t;
            float2 al = *reinterpret_cast<const float2*>(attn_l + cc);
            float2 ar = *reinterpret_cast<const float2*>(attn_r + cc);
            pll += c[nb][0] * al.x + c[nb][1] * al.y;
            plh += c[nb][2] * al.x + c[nb][3] * al.y;
            prl += c[nb][0] * ar.x + c[nb][1] * ar.y;
            prh += c[nb][2] * ar.x + c[nb][3] * ar.y;
        }
#pragma unroll
        for (int off = 1; off <= 2; off <<= 1) {
            pll += __shfl_xor_sync(~0u, pll, off);
            plh += __shfl_xor_sync(~0u, plh, off);
            prl += __shfl_xor_sync(~0u, prl, off);
            prh += __shfl_xor_sync(~0u, prh, off);
        }
        if (t == 0) {
            if (r_lo < N_NODES) { g_el[r_lo * NH + h] = pll; g_er[r_lo * NH + h] = prl; }
            if (r_hi < N_NODES) { g_el[r_hi * NH + h] = plh; g_er[r_hi * NH + h] = prh; }
        }
    }
}

// ---------------- CSR construction ----------------------------------------
__global__ void zero_deg_kernel() {
    int i = blockIdx.x * 256 + threadIdx.x;
    if (i < N_NODES) g_deg[i] = 0;
}

__global__ __launch_bounds__(256)
void hist_kernel(const int* __restrict__ dst) {
    int e = blockIdx.x * 256 + threadIdx.x;
    if (e < N_EDGES) atomicAdd(&g_deg[dst[e]], 1);
}

__global__ __launch_bounds__(256)
void chunk_sum_kernel() {
    __shared__ int s[8];
    int i = blockIdx.x * 256 + threadIdx.x;
    int v = (i < N_NODES) ? g_deg[i] : 0;
    for (int off = 16; off; off >>= 1) v += __shfl_xor_sync(~0u, v, off);
    if ((threadIdx.x & 31) == 0) s[threadIdx.x >> 5] = v;
    __syncthreads();
    if (threadIdx.x < 8) {
        int tv = s[threadIdx.x];
        for (int off = 4; off; off >>= 1) tv += __shfl_xor_sync(0xffu, tv, off);
        if (threadIdx.x == 0) g_part[blockIdx.x] = tv;
    }
}

__global__ __launch_bounds__(512)
void scan_part_kernel() {
    __shared__ int s[512];
    int t = threadIdx.x;
    int v = (t < NCHUNK) ? g_part[t] : 0;
    s[t] = v;
    __syncthreads();
    for (int d = 1; d < 512; d <<= 1) {
        int x = (t >= d) ? s[t - d] : 0;
        __syncthreads();
        s[t] += x;
        __syncthreads();
    }
    if (t < NCHUNK) g_part[t] = s[t] - v;
}

__global__ __launch_bounds__(256)
void scan_apply_kernel() {
    __shared__ int s[256];
    int i = blockIdx.x * 256 + threadIdx.x;
    int t = threadIdx.x;
    int v = (i < N_NODES) ? g_deg[i] : 0;
    s[t] = v;
    __syncthreads();
    for (int d = 1; d < 256; d <<= 1) {
        int x = (t >= d) ? s[t - d] : 0;
        __syncthreads();
        s[t] += x;
        __syncthreads();
    }
    if (i < N_NODES) {
        int off = g_part[blockIdx.x] + s[t] - v;
        g_off[i] = off;
        g_cur[i] = off;
    }
}

__global__ __launch_bounds__(256)
void scatter_kernel(const int* __restrict__ src, const int* __restrict__ dst) {
    int e = blockIdx.x * 256 + threadIdx.x;
    if (e >= N_EDGES) return;
    int pos = atomicAdd(&g_cur[dst[e]], 1);
    g_csr_src[pos] = src[e];
}

// ---------------- fused per-node softmax + aggregation (pipelined) ---------
// One warp per node, single CSR pass, no max shift (bounded logits).
// Chunks of 8 edges; next chunk's csr+el gather is prefetched before the
// current chunk's feature loop; feature loop gathers all 8 rows, then FMAs.
__global__ __launch_bounds__(256)
void node_kernel(float* __restrict__ rst) {
    int gw   = (blockIdx.x * 256 + threadIdx.x) >> 5;
    int lane = threadIdx.x & 31;
    if (gw >= N_NODES) return;

    const int beg = g_off[gw];
    const int deg = g_deg[gw];
    const int h    = lane >> 3;
    const int e_my = lane & 7;
    const float erh = __ldg(&g_er[gw * NH + h]);

    float4 acc = make_float4(0.f, 0.f, 0.f, 0.f);
    float wsum = 0.f;
    const int nfull = deg & ~7;            // full-chunk edge count

    // prologue: load chunk 0
    int   s_my  = 0;
    float lg_my = 0.f;
    if (nfull > 0) {
        s_my  = g_csr_src[beg + e_my];
        lg_my = __ldg(&g_el[s_my * NH + h]);
    }

    for (int base = 0; base < nfull; base += 8) {
        float a_val = __expf(lrelu(lg_my + erh));
        int   s_cur = s_my;
        // prefetch next chunk
        if (base + 8 < nfull) {
            s_my  = g_csr_src[beg + base + 8 + e_my];
            lg_my = __ldg(&g_el[s_my * NH + h]);
        }
        wsum += a_val;

        float aa[8]; int ss[8]; uint2 raw[8];
#pragma unroll
        for (int e = 0; e < 8; e++) {
            aa[e] = __shfl_sync(~0u, a_val, (lane & 24) | e);
            ss[e] = __shfl_sync(~0u, s_cur, e);
        }
#pragma unroll
        for (int e = 0; e < 8; e++)
            raw[e] = *reinterpret_cast<const uint2*>(&g_fth[ss[e] * HD + lane * 4]);
#pragma unroll
        for (int e = 0; e < 8; e++) {
            float2 f0 = __half22float2(*reinterpret_cast<__half2*>(&raw[e].x));
            float2 f1 = __half22float2(*reinterpret_cast<__half2*>(&raw[e].y));
            acc.x += aa[e] * f0.x; acc.y += aa[e] * f0.y;
            acc.z += aa[e] * f1.x; acc.w += aa[e] * f1.y;
        }
    }

    // remainder (< 8 edges)
    if (nfull < deg) {
        int nvalid = deg - nfull;
        float a_val = 0.f;
        int s_r = 0;
        if (e_my < nvalid) {
            s_r = g_csr_src[beg + nfull + e_my];
            a_val = __expf(lrelu(__ldg(&g_el[s_r * NH + h]) + erh));
        }
        wsum += a_val;
        for (int e = 0; e < nvalid; e++) {
            float a = __shfl_sync(~0u, a_val, (lane & 24) | e);
            int   s = __shfl_sync(~0u, s_r, e);
            uint2 raw = *reinterpret_cast<const uint2*>(&g_fth[s * HD + lane * 4]);
            float2 f0 = __half22float2(*reinterpret_cast<__half2*>(&raw.x));
            float2 f1 = __half22float2(*reinterpret_cast<__half2*>(&raw.y));
            acc.x += a * f0.x; acc.y += a * f0.y;
            acc.z += a * f1.x; acc.w += a * f1.y;
        }
    }

#pragma unroll
    for (int off = 1; off <= 4; off <<= 1)
        wsum += __shfl_xor_sync(~0u, wsum, off);
    float inv = (wsum > 0.f) ? __frcp_rn(wsum) : 0.f;

    acc.x *= inv; acc.y *= inv; acc.z *= inv; acc.w *= inv;
    *reinterpret_cast<float4*>(&rst[gw * HD + lane * 4]) = acc;
}

// ---------------- launch (single stream, allocation-free) ------------------
extern "C" void kernel_launch(void* const* d_in, const int* in_sizes, int n_in,
                              void* d_out, int out_size) {
    const float* feat   = (const float*)d_in[0];
    const float* W      = (const float*)d_in[1];
    const float* attn_l = (const float*)d_in[2];
    const float* attn_r = (const float*)d_in[3];
    const int*   src    = (const int*)d_in[4];
    const int*   dst    = (const int*)d_in[5];
    float*       rst    = (float*)d_out;

    cudaFuncSetAttribute(gemm_kernel, cudaFuncAttributeMaxDynamicSharedMemorySize,
                         GEMM_SMEM);

    int eb = (N_EDGES + 255) / 256;
    zero_deg_kernel<<<NCHUNK, 256>>>();
    hist_kernel<<<eb, 256>>>(dst);
    gemm_kernel<<<(N_NODES + 127) / 128, 256, GEMM_SMEM>>>(feat, W, attn_l, attn_r);
    chunk_sum_kernel<<<NCHUNK, 256>>>();
    scan_part_kernel<<<1, 512>>>();
    scan_apply_kernel<<<NCHUNK, 256>>>();
    scatter_kernel<<<eb, 256>>>(src, dst);
    node_kernel<<<(N_NODES * 32 + 255) / 256, 256>>>(rst);
}